// round 9
// baseline (speedup 1.0000x reference)
#include <cuda_runtime.h>
#include <cuda_bf16.h>
#include <mma.h>
#include <math.h>
#include <stdint.h>
using namespace nvcuda;

#define NB     4096          // batch rows
#define K_EXT  7936          // 7808 + 128 (h0 folded in)
#define N_G    512           // 4*LSTM_HIDDEN
#define TM     64
#define TN     64
#define BK     32
#define NSTAGE 3
#define NT     (K_EXT/BK)    // 248

// ---- scratch (device globals: allocation-free rule) ----
__device__ __align__(16) __nv_bfloat16 g_eah[300 * 128];   // ability emb hi
__device__ __align__(16) __nv_bfloat16 g_eal[300 * 128];   // ability emb lo
__device__ __align__(16) __nv_bfloat16 g_emh[900 * 128];   // move emb hi
__device__ __align__(16) __nv_bfloat16 g_eml[900 * 128];   // move emb lo
__device__ __align__(16) __nv_bfloat16 g_exh[(size_t)NB * 256];  // [num | h0] hi
__device__ __align__(16) __nv_bfloat16 g_exl[(size_t)NB * 256];  // [num | h0] lo
__device__ __align__(16) __nv_bfloat16 g_wh[(size_t)N_G * K_EXT];  // W hi [N][K]
__device__ __align__(16) __nv_bfloat16 g_wl[(size_t)N_G * K_EXT];  // W lo
__device__ __align__(16) float         g_gates[(size_t)NB * N_G];  // fp32 gates (no bias)

__device__ __forceinline__ void split2(float v, __nv_bfloat16& h, __nv_bfloat16& l) {
    h = __float2bfloat16(v);
    l = __float2bfloat16(v - __bfloat162float(h));
}

// ============================================================
// 1) embpack: ability/move tables -> bf16 hi/lo (L2-resident, read by GEMM)
// ============================================================
__global__ void embpack_kernel(const float* __restrict__ aemb, const float* __restrict__ memb)
{
    int r = blockIdx.x, t = threadIdx.x;
    if (r < 300) {
        __nv_bfloat16 h, l;
        split2(aemb[r * 128 + t], h, l);
        g_eah[r * 128 + t] = h;
        g_eal[r * 128 + t] = l;
    } else {
        int rr = r - 300;
        __nv_bfloat16 h, l;
        split2(memb[rr * 128 + t], h, l);
        g_emh[rr * 128 + t] = h;
        g_eml[rr * 128 + t] = l;
    }
}

// ============================================================
// 2) extrapack: numproj + h0 -> [B][256] bf16 hi/lo.
//    32 rows per block; num_W staged ONCE in smem (padded, conflict-free).
// ============================================================
#define EX_SMEM ((128 * 85 + 32 * 84) * 4)   // 54272 bytes

__global__ __launch_bounds__(256)
void extrapack_kernel(const float* __restrict__ numerical,
                      const float* __restrict__ num_W,
                      const float* __restrict__ num_b,
                      const float* __restrict__ h0)
{
    extern __shared__ float exsm[];
    float* Ws  = exsm;               // [128][85]
    float* nrs = exsm + 128 * 85;    // [32][84]
    const int tid = threadIdx.x;
    const int m0 = blockIdx.x * 32;

    for (int i = tid; i < 128 * 84; i += 256) {
        int t = i / 84, d = i - t * 84;
        Ws[t * 85 + d] = num_W[i];
    }
    for (int i = tid; i < 32 * 84; i += 256)
        nrs[i] = numerical[(size_t)m0 * 84 + i];
    __syncthreads();

    const int t = tid & 127, rbase = tid >> 7;
    const float nb = num_b[t];
    const float* w = Ws + t * 85;
    for (int rr = rbase; rr < 32; rr += 2) {
        const float* nr = nrs + rr * 84;
        float acc = nb;
        #pragma unroll 4
        for (int d = 0; d < 84; d++) acc += w[d] * nr[d];
        __nv_bfloat16 h, l;
        split2(acc, h, l);
        g_exh[(size_t)(m0 + rr) * 256 + t] = h;
        g_exl[(size_t)(m0 + rr) * 256 + t] = l;
    }
    for (int i = tid; i < 32 * 128; i += 256) {
        int r = i >> 7, d = i & 127;
        __nv_bfloat16 h, l;
        split2(h0[(size_t)(m0 + r) * 128 + d], h, l);
        g_exh[(size_t)(m0 + r) * 256 + 128 + d] = h;
        g_exl[(size_t)(m0 + r) * 256 + 128 + d] = l;
    }
}

// ============================================================
// 3) weight pack: [Wih | Whh] -> [512][7936] bf16 hi/lo, float4 vectorized
// ============================================================
__global__ void wpack_kernel(const float* __restrict__ Wih, const float* __restrict__ Whh)
{
    int n = blockIdx.x;
    for (int i4 = threadIdx.x; i4 < K_EXT / 4; i4 += 256) {
        int k = i4 * 4;
        float4 v = (k < 7808) ? *(const float4*)(Wih + (size_t)n * 7808 + k)
                              : *(const float4*)(Whh + n * 128 + (k - 7808));
        __nv_bfloat16 h0_, h1_, h2_, h3_, l0_, l1_, l2_, l3_;
        split2(v.x, h0_, l0_); split2(v.y, h1_, l1_);
        split2(v.z, h2_, l2_); split2(v.w, h3_, l3_);
        __nv_bfloat162 ph01{h0_, h1_}, ph23{h2_, h3_}, pl01{l0_, l1_}, pl23{l2_, l3_};
        uint2 uh, ul;
        uh.x = *(uint32_t*)&ph01; uh.y = *(uint32_t*)&ph23;
        ul.x = *(uint32_t*)&pl01; ul.y = *(uint32_t*)&pl23;
        size_t off = (size_t)n * K_EXT + k;
        *(uint2*)(g_wh + off) = uh;
        *(uint2*)(g_wl + off) = ul;
    }
}

// ============================================================
// 4) GEMM: gates[4096][512] = x @ W^T (3-term bf16 split)
//    CTA 64x64, warp tile 32x16 (2x4 warp grid), BK=32, cp.async 3-stage.
//    High-occupancy config: 512 CTAs, 3 CTAs/SM (24 warps/SM).
//    A gathered on-the-fly from emb tables via smem id table.
// ============================================================
#define LDP 40                          // padded leading dim (elements)
#define REG_B     (TM * LDP * 2)        // 5120 bytes per operand region
#define OFF_AL    (REG_B)               // 5120
#define OFF_BH    (2 * REG_B)           // 10240
#define OFF_BL    (3 * REG_B)           // 15360
#define STAGE_B   (4 * REG_B)           // 20480
#define IDS_B     (TM * 60 * 2)         // 7680 (u16 id table)
#define SM_STG    IDS_B
#define GEMM_SMEM (IDS_B + NSTAGE * STAGE_B)   // 69120

__device__ __forceinline__ uint32_t smem_u32(const void* p) {
    uint32_t a;
    asm("{ .reg .u64 t; cvta.to.shared.u64 t, %1; cvt.u32.u64 %0, t; }" : "=r"(a) : "l"(p));
    return a;
}
__device__ __forceinline__ void cp16(uint32_t s, const void* g) {
    asm volatile("cp.async.cg.shared.global [%0], [%1], 16;" :: "r"(s), "l"(g));
}

__global__ __launch_bounds__(256, 3)
void gemm_kernel(const int* __restrict__ aid, const int* __restrict__ mid)
{
    extern __shared__ char smbase[];
    const uint32_t sb = smem_u32(smbase);
    const int tid = threadIdx.x;
    const int n0 = blockIdx.x * TN;
    const int m0 = blockIdx.y * TM;

    // ---- load id table: sid[r][0..11]=ability, sid[r][12..59]=move ----
    uint16_t* sid = (uint16_t*)smbase;
    {
        const int* asrc = aid + (size_t)m0 * 12;     // 768 contiguous ints
        const int* msrc = mid + (size_t)m0 * 48;     // 3072 contiguous ints
        for (int i = tid; i < 768; i += 256) {
            int r = i / 12, s = i % 12;
            sid[r * 60 + s] = (uint16_t)asrc[i];
        }
        for (int i = tid; i < 3072; i += 256) {
            int r = i / 48, s = i % 48;
            sid[r * 60 + 12 + s] = (uint16_t)msrc[i];
        }
    }
    __syncthreads();

    // ---- per-thread cp.async roles: row r (0..63), 16B chunk cb (0..3) ----
    const int r  = tid >> 2;             // 0..63
    const int cb = tid & 3;              // 16B chunk within 64B k-row
    const uint32_t so_row = r * (LDP * 2) + cb * 16;
    const char* bsrc_h = (const char*)(g_wh + (size_t)(n0 + r) * K_EXT) + cb * 16;
    const char* bsrc_l = (const char*)(g_wl + (size_t)(n0 + r) * K_EXT) + cb * 16;

    auto prefetch = [&](int ss, int buf) {
        const uint32_t dst = sb + SM_STG + buf * STAGE_B;
        const char *ah, *al;
        if (ss < 240) {
            const int s = ss >> 2, d = (ss & 3) * 32;
            const int id = sid[r * 60 + s];
            if (s < 12) {
                ah = (const char*)(g_eah + id * 128 + d);
                al = (const char*)(g_eal + id * 128 + d);
            } else {
                ah = (const char*)(g_emh + id * 128 + d);
                al = (const char*)(g_eml + id * 128 + d);
            }
        } else {
            const int d = (ss - 240) * 32;
            ah = (const char*)(g_exh + (size_t)(m0 + r) * 256 + d);
            al = (const char*)(g_exl + (size_t)(m0 + r) * 256 + d);
        }
        cp16(dst + so_row,          ah + cb * 16);
        cp16(dst + OFF_AL + so_row, al + cb * 16);
        const size_t bk = (size_t)ss * (BK * 2);
        cp16(dst + OFF_BH + so_row, bsrc_h + bk);
        cp16(dst + OFF_BL + so_row, bsrc_l + bk);
        asm volatile("cp.async.commit_group;" ::: "memory");
    };

    const int wid = tid >> 5;
    const int wm = wid & 1;              // 2 warps along M (32 rows each)
    const int wn = wid >> 1;             // 4 warps along N (16 cols each)

    wmma::fragment<wmma::accumulator, 16, 16, 16, float> acc[2];
    #pragma unroll
    for (int i = 0; i < 2; i++) wmma::fill_fragment(acc[i], 0.0f);

    // ---- prologue: stages 0,1 in flight ----
    prefetch(0, 0);
    prefetch(1, 1);

    #pragma unroll 1
    for (int t = 0; t < NT; ++t) {
        asm volatile("cp.async.wait_group 1;" ::: "memory");
        __syncthreads();   // stage t visible; all warps done with stage t-1

        if (t + 2 < NT) {
            prefetch(t + 2, (t + 2) % NSTAGE);
        } else {
            asm volatile("cp.async.commit_group;" ::: "memory");  // keep group count uniform
        }

        const __nv_bfloat16* stg = (const __nv_bfloat16*)(smbase + SM_STG + (t % NSTAGE) * STAGE_B);
        const __nv_bfloat16* Ah = stg;
        const __nv_bfloat16* Al = stg + TM * LDP;
        const __nv_bfloat16* Bh = stg + 2 * TM * LDP;
        const __nv_bfloat16* Bl = stg + 3 * TM * LDP;

        #pragma unroll
        for (int sub = 0; sub < 2; sub++) {
            const int k16 = sub * 16;
            wmma::fragment<wmma::matrix_a, 16, 16, 16, __nv_bfloat16, wmma::row_major> fa_h[2], fa_l[2];
            wmma::fragment<wmma::matrix_b, 16, 16, 16, __nv_bfloat16, wmma::col_major> fb_h, fb_l;
            #pragma unroll
            for (int i = 0; i < 2; i++) {
                wmma::load_matrix_sync(fa_h[i], Ah + (wm * 32 + i * 16) * LDP + k16, LDP);
                wmma::load_matrix_sync(fa_l[i], Al + (wm * 32 + i * 16) * LDP + k16, LDP);
            }
            wmma::load_matrix_sync(fb_h, Bh + (wn * 16) * LDP + k16, LDP);
            wmma::load_matrix_sync(fb_l, Bl + (wn * 16) * LDP + k16, LDP);
            #pragma unroll
            for (int i = 0; i < 2; i++) {
                wmma::mma_sync(acc[i], fa_h[i], fb_h, acc[i]);
                wmma::mma_sync(acc[i], fa_l[i], fb_h, acc[i]);
                wmma::mma_sync(acc[i], fa_h[i], fb_l, acc[i]);
            }
        }
    }

    // ---- epilogue: accum -> smem -> g_gates (tail adds biases) ----
    asm volatile("cp.async.wait_group 0;" ::: "memory");
    __syncthreads();
    float* Cs = (float*)smbase;   // [64][68]
    #pragma unroll
    for (int i = 0; i < 2; i++)
        wmma::store_matrix_sync(Cs + (wm * 32 + i * 16) * 68 + wn * 16,
                                acc[i], 68, wmma::mem_row_major);
    __syncthreads();
    for (int idx = tid; idx < TM * TN / 4; idx += 256) {
        int m = idx >> 4, n4 = (idx & 15) * 4;
        float4 v = *(float4*)(Cs + m * 68 + n4);
        *(float4*)(g_gates + (size_t)(m0 + m) * N_G + n0 + n4) = v;
    }
}

// ============================================================
// 5) tail: bias + LSTM elementwise + MLP head + softmax + masked renorm
// ============================================================
__device__ __forceinline__ float sigm(float x) { return 1.0f / (1.0f + expf(-x)); }

#define OFF_H1 (NB * 9)
#define OFF_C1 (NB * 9 + NB * 128)

__global__ __launch_bounds__(128)
void tail_kernel(const float* __restrict__ c0,
                 const float* __restrict__ bih, const float* __restrict__ bhh,
                 const float* __restrict__ W1, const float* __restrict__ b1,
                 const float* __restrict__ W2, const float* __restrict__ b2,
                 const float* __restrict__ Wa, const float* __restrict__ ba,
                 const float* __restrict__ mask, float* __restrict__ out)
{
    __shared__ float W1t[128 * 65];   // [d][j], padded: conflict-free R & W
    __shared__ float Was[9 * 129];    // padded: conflict-free across 9 lanes
    __shared__ float b1s[64], b2s[128], bas[9];
    __shared__ float h1s[128], feats[64], es[128], lgs[9];

    const int t = threadIdx.x;
    for (int i = t; i < 64 * 128; i += 128) {     // coalesced read of W1 [64][128]
        int j = i >> 7, d = i & 127;
        W1t[d * 65 + j] = W1[i];
    }
    for (int i = t; i < 9 * 128; i += 128) {
        int j = i >> 7, d = i & 127;
        Was[j * 129 + d] = Wa[i];
    }
    if (t < 64) b1s[t] = b1[t];
    b2s[t] = b2[t];
    if (t < 9) bas[t] = ba[t];
    const float bi = bih[t]       + bhh[t];
    const float bf = bih[128 + t] + bhh[128 + t];
    const float bg = bih[256 + t] + bhh[256 + t];
    const float bo = bih[384 + t] + bhh[384 + t];
    __syncthreads();

    for (int r = 0; r < 8; r++) {
        const int b = blockIdx.x * 8 + r;
        const float* g = g_gates + (size_t)b * N_G;
        float ii = sigm(g[t] + bi);
        float ff = sigm(g[128 + t] + bf);
        float gg = tanhf(g[256 + t] + bg);
        float oo = sigm(g[384 + t] + bo);
        float c1 = ff * c0[(size_t)b * 128 + t] + ii * gg;
        float h1 = oo * tanhf(c1);
        out[OFF_H1 + (size_t)b * 128 + t] = h1;
        out[OFF_C1 + (size_t)b * 128 + t] = c1;
        h1s[t] = h1;
        __syncthreads();

        if (t < 64) {
            float a = b1s[t];
            #pragma unroll 8
            for (int d = 0; d < 128; d++) a += W1t[d * 65 + t] * h1s[d];
            feats[t] = fmaxf(a, 0.0f);
        }
        __syncthreads();

        {
            float a = b2s[t];
            const float* w = W2 + t * 64;   // small, L1-resident
            #pragma unroll 8
            for (int d = 0; d < 64; d++) a += w[d] * feats[d];
            es[t] = a;
        }
        __syncthreads();

        if (t < 9) {
            float a = bas[t];
            const float* w = Was + t * 129;
            #pragma unroll 8
            for (int d = 0; d < 128; d++) a += w[d] * es[d];
            lgs[t] = a;
        }
        __syncthreads();

        if (t == 0) {
            float lg[9];
            float mx = -1e30f;
            #pragma unroll
            for (int j = 0; j < 9; j++) { lg[j] = lgs[j]; mx = fmaxf(mx, lg[j]); }
            float se = 0.0f;
            #pragma unroll
            for (int j = 0; j < 9; j++) { lg[j] = expf(lg[j] - mx); se += lg[j]; }
            float inv = 1.0f / se;
            float p[9], mk[9], msum = 0.0f;
            #pragma unroll
            for (int j = 0; j < 9; j++) {
                p[j] = lg[j] * inv;
                mk[j] = p[j] * mask[(size_t)b * 9 + j];
                msum += mk[j];
            }
            if (msum > 0.0f) {
                float minv = 1.0f / msum;
                #pragma unroll
                for (int j = 0; j < 9; j++) out[(size_t)b * 9 + j] = mk[j] * minv;
            } else {
                #pragma unroll
                for (int j = 0; j < 9; j++) out[(size_t)b * 9 + j] = p[j];
            }
        }
        __syncthreads();
    }
}

// ============================================================
// launcher
// ============================================================
extern "C" void kernel_launch(void* const* d_in, const int* in_sizes, int n_in,
                              void* d_out, int out_size)
{
    const int*   ability_ids = (const int*)d_in[0];
    const int*   move_ids    = (const int*)d_in[1];
    const float* numerical   = (const float*)d_in[2];
    const float* mask        = (const float*)d_in[3];
    const float* h0          = (const float*)d_in[4];
    const float* c0          = (const float*)d_in[5];
    const float* ability_emb = (const float*)d_in[6];
    const float* move_emb    = (const float*)d_in[7];
    const float* num_W       = (const float*)d_in[8];
    const float* num_b       = (const float*)d_in[9];
    const float* Wih         = (const float*)d_in[10];
    const float* Whh         = (const float*)d_in[11];
    const float* bih         = (const float*)d_in[12];
    const float* bhh         = (const float*)d_in[13];
    const float* W1          = (const float*)d_in[14];
    const float* b1          = (const float*)d_in[15];
    const float* W2          = (const float*)d_in[16];
    const float* b2          = (const float*)d_in[17];
    const float* Wa          = (const float*)d_in[18];
    const float* ba          = (const float*)d_in[19];
    float* out = (float*)d_out;

    cudaFuncSetAttribute(gemm_kernel, cudaFuncAttributeMaxDynamicSharedMemorySize, GEMM_SMEM);
    cudaFuncSetAttribute(extrapack_kernel, cudaFuncAttributeMaxDynamicSharedMemorySize, EX_SMEM);

    embpack_kernel<<<1200, 128>>>(ability_emb, move_emb);
    extrapack_kernel<<<NB / 32, 256, EX_SMEM>>>(numerical, num_W, num_b, h0);
    wpack_kernel<<<N_G, 256>>>(Wih, Whh);
    gemm_kernel<<<dim3(N_G / TN, NB / TM), 256, GEMM_SMEM>>>(ability_ids, move_ids);
    tail_kernel<<<NB / 8, 128>>>(c0, bih, bhh, W1, b1, W2, b2, Wa, ba, mask, out);
}

// round 10
// speedup vs baseline: 2.0617x; 2.0617x over previous
#include <cuda_runtime.h>
#include <cuda_bf16.h>
#include <math.h>
#include <stdint.h>

#define NB     4096          // batch rows
#define K_EXT  7936          // 7808 + 128 (h0 folded in)
#define N_G    512           // 4*LSTM_HIDDEN
#define TM     128
#define TN     64
#define BK     32
#define NSTAGE 3
#define NT     (K_EXT/BK)    // 248

// ---- scratch (device globals: allocation-free rule) ----
__device__ __align__(16) __nv_bfloat16 g_eah[300 * 128];   // ability emb hi
__device__ __align__(16) __nv_bfloat16 g_eal[300 * 128];   // ability emb lo
__device__ __align__(16) __nv_bfloat16 g_emh[900 * 128];   // move emb hi
__device__ __align__(16) __nv_bfloat16 g_eml[900 * 128];   // move emb lo
__device__ __align__(16) __nv_bfloat16 g_exh[(size_t)NB * 256];  // [num | h0] hi
__device__ __align__(16) __nv_bfloat16 g_exl[(size_t)NB * 256];  // [num | h0] lo
__device__ __align__(16) __nv_bfloat16 g_wh[(size_t)N_G * K_EXT];  // W hi [N][K]
__device__ __align__(16) __nv_bfloat16 g_wl[(size_t)N_G * K_EXT];  // W lo
__device__ __align__(16) float         g_gates[(size_t)NB * N_G];  // fp32 gates (no bias)

__device__ __forceinline__ void split2(float v, __nv_bfloat16& h, __nv_bfloat16& l) {
    h = __float2bfloat16(v);
    l = __float2bfloat16(v - __bfloat162float(h));
}

// ============================================================
// 1) embpack: ability/move tables -> bf16 hi/lo (L2-resident, read by GEMM)
// ============================================================
__global__ void embpack_kernel(const float* __restrict__ aemb, const float* __restrict__ memb)
{
    int r = blockIdx.x, t = threadIdx.x;
    if (r < 300) {
        __nv_bfloat16 h, l;
        split2(aemb[r * 128 + t], h, l);
        g_eah[r * 128 + t] = h;
        g_eal[r * 128 + t] = l;
    } else {
        int rr = r - 300;
        __nv_bfloat16 h, l;
        split2(memb[rr * 128 + t], h, l);
        g_emh[rr * 128 + t] = h;
        g_eml[rr * 128 + t] = l;
    }
}

// ============================================================
// 2) extrapack: numproj + h0 -> [B][256] bf16 hi/lo.
//    32 rows per block; num_W staged ONCE in smem (padded, conflict-free).
// ============================================================
#define EX_SMEM ((128 * 85 + 32 * 84) * 4)   // 54272 bytes

__global__ __launch_bounds__(256)
void extrapack_kernel(const float* __restrict__ numerical,
                      const float* __restrict__ num_W,
                      const float* __restrict__ num_b,
                      const float* __restrict__ h0)
{
    extern __shared__ float exsm[];
    float* Ws  = exsm;               // [128][85]
    float* nrs = exsm + 128 * 85;    // [32][84]
    const int tid = threadIdx.x;
    const int m0 = blockIdx.x * 32;

    for (int i = tid; i < 128 * 84; i += 256) {
        int t = i / 84, d = i - t * 84;
        Ws[t * 85 + d] = num_W[i];
    }
    for (int i = tid; i < 32 * 84; i += 256)
        nrs[i] = numerical[(size_t)m0 * 84 + i];
    __syncthreads();

    const int t = tid & 127, rbase = tid >> 7;
    const float nb = num_b[t];
    const float* w = Ws + t * 85;
    for (int rr = rbase; rr < 32; rr += 2) {
        const float* nr = nrs + rr * 84;
        float acc = nb;
        #pragma unroll 4
        for (int d = 0; d < 84; d++) acc += w[d] * nr[d];
        __nv_bfloat16 h, l;
        split2(acc, h, l);
        g_exh[(size_t)(m0 + rr) * 256 + t] = h;
        g_exl[(size_t)(m0 + rr) * 256 + t] = l;
    }
    for (int i = tid; i < 32 * 128; i += 256) {
        int r = i >> 7, d = i & 127;
        __nv_bfloat16 h, l;
        split2(h0[(size_t)(m0 + r) * 128 + d], h, l);
        g_exh[(size_t)(m0 + r) * 256 + 128 + d] = h;
        g_exl[(size_t)(m0 + r) * 256 + 128 + d] = l;
    }
}

// ============================================================
// 3) weight pack: [Wih | Whh] -> [512][7936] bf16 hi/lo, float4 vectorized
// ============================================================
__global__ void wpack_kernel(const float* __restrict__ Wih, const float* __restrict__ Whh)
{
    int n = blockIdx.x;
    for (int i4 = threadIdx.x; i4 < K_EXT / 4; i4 += 256) {
        int k = i4 * 4;
        float4 v = (k < 7808) ? *(const float4*)(Wih + (size_t)n * 7808 + k)
                              : *(const float4*)(Whh + n * 128 + (k - 7808));
        __nv_bfloat16 h0_, h1_, h2_, h3_, l0_, l1_, l2_, l3_;
        split2(v.x, h0_, l0_); split2(v.y, h1_, l1_);
        split2(v.z, h2_, l2_); split2(v.w, h3_, l3_);
        __nv_bfloat162 ph01{h0_, h1_}, ph23{h2_, h3_}, pl01{l0_, l1_}, pl23{l2_, l3_};
        uint2 uh, ul;
        uh.x = *(uint32_t*)&ph01; uh.y = *(uint32_t*)&ph23;
        ul.x = *(uint32_t*)&pl01; ul.y = *(uint32_t*)&pl23;
        size_t off = (size_t)n * K_EXT + k;
        *(uint2*)(g_wh + off) = uh;
        *(uint2*)(g_wl + off) = ul;
    }
}

// ============================================================
// 4) GEMM: gates[4096][512] = x @ W^T (3-term bf16 split)
//    CTA 128x64, warp tile 32x32, BK=32, cp.async 3-stage pipeline.
//    Raw PTX ldmatrix + mma.sync.m16n8k16 (flat dependency graph).
//    A gathered on-the-fly from emb tables via smem id table.
// ============================================================
#define LDP 40                          // padded leading dim (elements)
#define A_STAGE_B (TM * LDP * 2)        // 10240 bytes per (hi|lo)
#define B_STAGE_B (TN * LDP * 2)        // 5120 bytes per (hi|lo)
#define OFF_AL    (A_STAGE_B)           // 10240
#define OFF_BH    (2 * A_STAGE_B)       // 20480
#define OFF_BL    (2 * A_STAGE_B + B_STAGE_B)  // 25600
#define STAGE_B   (2 * A_STAGE_B + 2 * B_STAGE_B)  // 30720
#define IDS_B     (128 * 60 * 2)        // 15360 (u16 id table)
#define SM_STG    IDS_B
#define GEMM_SMEM (IDS_B + NSTAGE * STAGE_B)   // 107520

__device__ __forceinline__ uint32_t smem_u32(const void* p) {
    uint32_t a;
    asm("{ .reg .u64 t; cvta.to.shared.u64 t, %1; cvt.u32.u64 %0, t; }" : "=r"(a) : "l"(p));
    return a;
}
__device__ __forceinline__ void cp16(uint32_t s, const void* g) {
    asm volatile("cp.async.cg.shared.global [%0], [%1], 16;" :: "r"(s), "l"(g));
}
#define LDSM4(r, addr) \
    asm volatile("ldmatrix.sync.aligned.m8n8.x4.shared.b16 {%0,%1,%2,%3}, [%4];" \
        : "=r"((r)[0]), "=r"((r)[1]), "=r"((r)[2]), "=r"((r)[3]) : "r"(addr))
#define MMA16816(c, a, b0, b1) \
    asm volatile("mma.sync.aligned.m16n8k16.row.col.f32.bf16.bf16.f32 " \
        "{%0,%1,%2,%3}, {%4,%5,%6,%7}, {%8,%9}, {%0,%1,%2,%3};" \
        : "+f"((c)[0]), "+f"((c)[1]), "+f"((c)[2]), "+f"((c)[3]) \
        : "r"((a)[0]), "r"((a)[1]), "r"((a)[2]), "r"((a)[3]), "r"(b0), "r"(b1))

__global__ __launch_bounds__(256, 2)
void gemm_kernel(const int* __restrict__ aid, const int* __restrict__ mid)
{
    extern __shared__ char smbase[];
    const uint32_t sb = smem_u32(smbase);
    const int tid = threadIdx.x;
    const int n0 = blockIdx.x * TN;
    const int m0 = blockIdx.y * TM;

    // ---- load id table: sid[r][0..11]=ability, sid[r][12..59]=move ----
    uint16_t* sid = (uint16_t*)smbase;
    {
        const int* asrc = aid + (size_t)m0 * 12;     // 1536 contiguous ints
        const int* msrc = mid + (size_t)m0 * 48;     // 6144 contiguous ints
        for (int i = tid; i < 1536; i += 256) {
            int r = i / 12, s = i % 12;
            sid[r * 60 + s] = (uint16_t)asrc[i];
        }
        for (int i = tid; i < 6144; i += 256) {
            int r = i / 48, s = i % 48;
            sid[r * 60 + 12 + s] = (uint16_t)msrc[i];
        }
    }
    __syncthreads();

    // ---- per-thread cp.async roles: A rows r0, r0+64 (hi+lo), B row r0, chunk c ----
    const int r0 = tid >> 2;             // 0..63
    const int r1 = r0 + 64;
    const int c  = tid & 3;              // 16B chunk within 64B k-row
    const uint32_t soff_a0h = r0 * (LDP * 2) + c * 16;
    const uint32_t soff_a1h = r1 * (LDP * 2) + c * 16;
    const uint32_t soff_a0l = OFF_AL + r0 * (LDP * 2) + c * 16;
    const uint32_t soff_a1l = OFF_AL + r1 * (LDP * 2) + c * 16;
    const uint32_t soff_bh  = OFF_BH + r0 * (LDP * 2) + c * 16;
    const uint32_t soff_bl  = OFF_BL + r0 * (LDP * 2) + c * 16;
    const char* bsrc_h = (const char*)(g_wh + (size_t)(n0 + r0) * K_EXT) + c * 16;
    const char* bsrc_l = (const char*)(g_wl + (size_t)(n0 + r0) * K_EXT) + c * 16;

    auto prefetch = [&](int ss, int buf) {
        const uint32_t dst = sb + SM_STG + buf * STAGE_B;
        const int k = ss * BK + c * 8;
        const char *a0h, *a1h, *a0l, *a1l;
        if (k < 7680) {
            const int s = k >> 7, d = k & 127;
            const int id0 = sid[r0 * 60 + s];
            const int id1 = sid[r1 * 60 + s];
            if (s < 12) {
                a0h = (const char*)(g_eah + id0 * 128 + d);
                a0l = (const char*)(g_eal + id0 * 128 + d);
                a1h = (const char*)(g_eah + id1 * 128 + d);
                a1l = (const char*)(g_eal + id1 * 128 + d);
            } else {
                a0h = (const char*)(g_emh + id0 * 128 + d);
                a0l = (const char*)(g_eml + id0 * 128 + d);
                a1h = (const char*)(g_emh + id1 * 128 + d);
                a1l = (const char*)(g_eml + id1 * 128 + d);
            }
        } else {
            const int d = k - 7680;
            a0h = (const char*)(g_exh + (size_t)(m0 + r0) * 256 + d);
            a0l = (const char*)(g_exl + (size_t)(m0 + r0) * 256 + d);
            a1h = (const char*)(g_exh + (size_t)(m0 + r1) * 256 + d);
            a1l = (const char*)(g_exl + (size_t)(m0 + r1) * 256 + d);
        }
        cp16(dst + soff_a0h, a0h);
        cp16(dst + soff_a1h, a1h);
        cp16(dst + soff_a0l, a0l);
        cp16(dst + soff_a1l, a1l);
        cp16(dst + soff_bh, bsrc_h + (size_t)ss * (BK * 2));
        cp16(dst + soff_bl, bsrc_l + (size_t)ss * (BK * 2));
        asm volatile("cp.async.commit_group;" ::: "memory");
    };

    const int wid = tid >> 5;
    const int lane = tid & 31;
    const int wm = wid & 3;              // 4 warps along M (32 rows each)
    const int wn = wid >> 2;             // 2 warps along N (32 cols each)

    // ---- ldmatrix lane-address element offsets (within stage, in elements) ----
    // A (row-major m16k16, x4): lanes 0-7 rows0-7 k0-7 | 8-15 rows8-15 k0-7 |
    //                           16-23 rows0-7 k8-15 | 24-31 rows8-15 k8-15
    const int arow = lane & 15;
    const int akh  = (lane >> 4) << 3;
    int aoff[2];
    #pragma unroll
    for (int i = 0; i < 2; i++)
        aoff[i] = (wm * 32 + i * 16 + arow) * LDP + akh;
    // B ([n][k] k-contig, x4 covers two n8 tiles):
    // lanes 0-7: n0-7 k0-7 | 8-15: n0-7 k8-15 | 16-23: n8-15 k0-7 | 24-31: n8-15 k8-15
    const int bn  = (lane & 7) + ((lane >> 4) << 3);
    const int bkh = ((lane >> 3) & 1) << 3;
    int boff[2];
    #pragma unroll
    for (int p = 0; p < 2; p++)
        boff[p] = (wn * 32 + p * 16 + bn) * LDP + bkh;

    float acc[2][4][4];   // [m-tile][n8-tile][frag]
    #pragma unroll
    for (int i = 0; i < 2; i++)
        #pragma unroll
        for (int j = 0; j < 4; j++)
            #pragma unroll
            for (int q = 0; q < 4; q++) acc[i][j][q] = 0.0f;

    // ---- prologue: stages 0,1 in flight ----
    prefetch(0, 0);
    prefetch(1, 1);

    #pragma unroll 1
    for (int t = 0; t < NT; ++t) {
        asm volatile("cp.async.wait_group 1;" ::: "memory");
        __syncthreads();   // stage t visible; all warps done with stage t-1

        if (t + 2 < NT) {
            prefetch(t + 2, (t + 2) % NSTAGE);
        } else {
            asm volatile("cp.async.commit_group;" ::: "memory");  // keep group count uniform
        }

        const uint32_t stg_u = sb + SM_STG + (t % NSTAGE) * STAGE_B;
        const uint32_t Ah_u = stg_u;
        const uint32_t Al_u = stg_u + OFF_AL;
        const uint32_t Bh_u = stg_u + OFF_BH;
        const uint32_t Bl_u = stg_u + OFF_BL;

        #pragma unroll
        for (int sub = 0; sub < 2; sub++) {
            const int k16 = sub * 16;
            uint32_t ah[2][4], al[2][4], bh[2][4], bl[2][4];
            // 8 independent LDSM.x4 up front (MLP)
            #pragma unroll
            for (int i = 0; i < 2; i++) {
                LDSM4(ah[i], Ah_u + (uint32_t)(aoff[i] + k16) * 2);
                LDSM4(al[i], Al_u + (uint32_t)(aoff[i] + k16) * 2);
            }
            #pragma unroll
            for (int p = 0; p < 2; p++) {
                LDSM4(bh[p], Bh_u + (uint32_t)(boff[p] + k16) * 2);
                LDSM4(bl[p], Bl_u + (uint32_t)(boff[p] + k16) * 2);
            }
            // 24 mmas across 8 independent accumulator tiles
            #pragma unroll
            for (int i = 0; i < 2; i++)
                #pragma unroll
                for (int j = 0; j < 4; j++) {
                    const int p = j >> 1, h = (j & 1) * 2;
                    MMA16816(acc[i][j], ah[i], bh[p][h], bh[p][h + 1]);
                    MMA16816(acc[i][j], al[i], bh[p][h], bh[p][h + 1]);
                    MMA16816(acc[i][j], ah[i], bl[p][h], bl[p][h + 1]);
                }
        }
    }

    // ---- epilogue: direct coalesced STG.64 from accumulators (tail adds biases) ----
    asm volatile("cp.async.wait_group 0;" ::: "memory");
    const int erow = lane >> 2;          // 0..7
    const int ecol = (lane & 3) * 2;     // 0,2,4,6
    #pragma unroll
    for (int i = 0; i < 2; i++) {
        #pragma unroll
        for (int j = 0; j < 4; j++) {
            const int gm = m0 + wm * 32 + i * 16 + erow;
            const int gn = n0 + wn * 32 + j * 8 + ecol;
            float2 v0{acc[i][j][0], acc[i][j][1]};
            float2 v1{acc[i][j][2], acc[i][j][3]};
            *(float2*)(g_gates + (size_t)gm * N_G + gn) = v0;
            *(float2*)(g_gates + (size_t)(gm + 8) * N_G + gn) = v1;
        }
    }
}

// ============================================================
// 5) tail: bias + LSTM elementwise + MLP head + softmax + masked renorm
// ============================================================
__device__ __forceinline__ float sigm(float x) { return 1.0f / (1.0f + expf(-x)); }

#define OFF_H1 (NB * 9)
#define OFF_C1 (NB * 9 + NB * 128)

__global__ __launch_bounds__(128)
void tail_kernel(const float* __restrict__ c0,
                 const float* __restrict__ bih, const float* __restrict__ bhh,
                 const float* __restrict__ W1, const float* __restrict__ b1,
                 const float* __restrict__ W2, const float* __restrict__ b2,
                 const float* __restrict__ Wa, const float* __restrict__ ba,
                 const float* __restrict__ mask, float* __restrict__ out)
{
    __shared__ float W1t[128 * 65];   // [d][j], padded: conflict-free R & W
    __shared__ float Was[9 * 129];    // padded: conflict-free across 9 lanes
    __shared__ float b1s[64], b2s[128], bas[9];
    __shared__ float h1s[128], feats[64], es[128], lgs[9];

    const int t = threadIdx.x;
    for (int i = t; i < 64 * 128; i += 128) {     // coalesced read of W1 [64][128]
        int j = i >> 7, d = i & 127;
        W1t[d * 65 + j] = W1[i];
    }
    for (int i = t; i < 9 * 128; i += 128) {
        int j = i >> 7, d = i & 127;
        Was[j * 129 + d] = Wa[i];
    }
    if (t < 64) b1s[t] = b1[t];
    b2s[t] = b2[t];
    if (t < 9) bas[t] = ba[t];
    const float bi = bih[t]       + bhh[t];
    const float bf = bih[128 + t] + bhh[128 + t];
    const float bg = bih[256 + t] + bhh[256 + t];
    const float bo = bih[384 + t] + bhh[384 + t];
    __syncthreads();

    for (int r = 0; r < 8; r++) {
        const int b = blockIdx.x * 8 + r;
        const float* g = g_gates + (size_t)b * N_G;
        float ii = sigm(g[t] + bi);
        float ff = sigm(g[128 + t] + bf);
        float gg = tanhf(g[256 + t] + bg);
        float oo = sigm(g[384 + t] + bo);
        float c1 = ff * c0[(size_t)b * 128 + t] + ii * gg;
        float h1 = oo * tanhf(c1);
        out[OFF_H1 + (size_t)b * 128 + t] = h1;
        out[OFF_C1 + (size_t)b * 128 + t] = c1;
        h1s[t] = h1;
        __syncthreads();

        if (t < 64) {
            float a = b1s[t];
            #pragma unroll 8
            for (int d = 0; d < 128; d++) a += W1t[d * 65 + t] * h1s[d];
            feats[t] = fmaxf(a, 0.0f);
        }
        __syncthreads();

        {
            float a = b2s[t];
            const float* w = W2 + t * 64;   // small, L1-resident
            #pragma unroll 8
            for (int d = 0; d < 64; d++) a += w[d] * feats[d];
            es[t] = a;
        }
        __syncthreads();

        if (t < 9) {
            float a = bas[t];
            const float* w = Was + t * 129;
            #pragma unroll 8
            for (int d = 0; d < 128; d++) a += w[d] * es[d];
            lgs[t] = a;
        }
        __syncthreads();

        if (t == 0) {
            float lg[9];
            float mx = -1e30f;
            #pragma unroll
            for (int j = 0; j < 9; j++) { lg[j] = lgs[j]; mx = fmaxf(mx, lg[j]); }
            float se = 0.0f;
            #pragma unroll
            for (int j = 0; j < 9; j++) { lg[j] = expf(lg[j] - mx); se += lg[j]; }
            float inv = 1.0f / se;
            float p[9], mk[9], msum = 0.0f;
            #pragma unroll
            for (int j = 0; j < 9; j++) {
                p[j] = lg[j] * inv;
                mk[j] = p[j] * mask[(size_t)b * 9 + j];
                msum += mk[j];
            }
            if (msum > 0.0f) {
                float minv = 1.0f / msum;
                #pragma unroll
                for (int j = 0; j < 9; j++) out[(size_t)b * 9 + j] = mk[j] * minv;
            } else {
                #pragma unroll
                for (int j = 0; j < 9; j++) out[(size_t)b * 9 + j] = p[j];
            }
        }
        __syncthreads();
    }
}

// ============================================================
// launcher
// ============================================================
extern "C" void kernel_launch(void* const* d_in, const int* in_sizes, int n_in,
                              void* d_out, int out_size)
{
    const int*   ability_ids = (const int*)d_in[0];
    const int*   move_ids    = (const int*)d_in[1];
    const float* numerical   = (const float*)d_in[2];
    const float* mask        = (const float*)d_in[3];
    const float* h0          = (const float*)d_in[4];
    const float* c0          = (const float*)d_in[5];
    const float* ability_emb = (const float*)d_in[6];
    const float* move_emb    = (const float*)d_in[7];
    const float* num_W       = (const float*)d_in[8];
    const float* num_b       = (const float*)d_in[9];
    const float* Wih         = (const float*)d_in[10];
    const float* Whh         = (const float*)d_in[11];
    const float* bih         = (const float*)d_in[12];
    const float* bhh         = (const float*)d_in[13];
    const float* W1          = (const float*)d_in[14];
    const float* b1          = (const float*)d_in[15];
    const float* W2          = (const float*)d_in[16];
    const float* b2          = (const float*)d_in[17];
    const float* Wa          = (const float*)d_in[18];
    const float* ba          = (const float*)d_in[19];
    float* out = (float*)d_out;

    cudaFuncSetAttribute(gemm_kernel, cudaFuncAttributeMaxDynamicSharedMemorySize, GEMM_SMEM);
    cudaFuncSetAttribute(extrapack_kernel, cudaFuncAttributeMaxDynamicSharedMemorySize, EX_SMEM);

    embpack_kernel<<<1200, 128>>>(ability_emb, move_emb);
    extrapack_kernel<<<NB / 32, 256, EX_SMEM>>>(numerical, num_W, num_b, h0);
    wpack_kernel<<<N_G, 256>>>(Wih, Whh);
    gemm_kernel<<<dim3(N_G / TN, NB / TM), 256, GEMM_SMEM>>>(ability_ids, move_ids);
    tail_kernel<<<NB / 8, 128>>>(c0, bih, bhh, W1, b1, W2, b2, Wa, ba, mask, out);
}